// round 1
// baseline (speedup 1.0000x reference)
#include <cuda_runtime.h>
#include <math.h>

#define BZ   128
#define T    32
#define D    768
#define DFF  3072
#define NE   8
#define NROWS 256                 // BZ * BEAMS
#define OUT_ELEMS (NROWS*T*D)     // 6291456
#define MAX_TILES 72

// ---------------- scratch (__device__ globals; no allocations allowed) ------
__device__ float g_xavg[BZ*D];
__device__ int   g_sel[NROWS];
__device__ int   g_perm[NROWS];
__device__ int   g_tile_e[MAX_TILES];
__device__ int   g_tile_p0[MAX_TILES];
__device__ int   g_tile_rows[MAX_TILES];
__device__ int   g_ntiles;
__device__ float g_h[(size_t)NROWS*T*DFF];   // 100.7 MB intermediate (grouped order)

__device__ __forceinline__ float gelu_exact(float v) {
    return 0.5f * v * (1.0f + erff(v * 0.70710678118654752f));
}

// ---------------- kernel 1: x_avg = mean over T ----------------------------
__global__ void avg_kernel(const float* __restrict__ x) {
    int b = blockIdx.x;
    for (int d = threadIdx.x; d < D; d += blockDim.x) {
        float s = 0.f;
        #pragma unroll
        for (int t = 0; t < T; t++)
            s += x[((size_t)b*T + t)*D + d];
        g_xavg[b*D + d] = s * (1.0f / T);
    }
}

// ---------------- kernel 2: router (logits, softmax, top-2) ----------------
// one warp per batch row. Writes sel[], and beam_scores / expert_route into
// the tail of d_out (assumed layout: [out | beam_scores | expert_route]).
__global__ void router_kernel(const float* __restrict__ Wg,
                              float* __restrict__ dout, int out_size) {
    int b = blockIdx.x;
    int lane = threadIdx.x;            // 32 lanes
    int e = lane & 7;                  // expert
    int chunk = lane >> 3;             // 0..3, 192 dims each
    float part = 0.f;
    const float* xa = g_xavg + b*D;
    for (int d = chunk*192; d < (chunk+1)*192; d++)
        part += xa[d] * Wg[d*NE + e];
    part += __shfl_down_sync(0xffffffffu, part, 16);
    part += __shfl_down_sync(0xffffffffu, part, 8);
    // lanes 0..7 hold logits; gather to all lanes
    float lv[NE];
    #pragma unroll
    for (int i = 0; i < NE; i++)
        lv[i] = __shfl_sync(0xffffffffu, part, i);

    if (lane == 0) {
        float mx = lv[0];
        #pragma unroll
        for (int i = 1; i < NE; i++) mx = fmaxf(mx, lv[i]);
        float p[NE]; float sum = 0.f;
        #pragma unroll
        for (int i = 0; i < NE; i++) { p[i] = __expf(lv[i] - mx); sum += p[i]; }
        float inv = 1.0f / sum;
        #pragma unroll
        for (int i = 0; i < NE; i++) p[i] *= inv;
        // top-2 (first occurrence on ties, matching jax top_k)
        int i0 = 0;
        #pragma unroll
        for (int i = 1; i < NE; i++) if (p[i] > p[i0]) i0 = i;
        int i1 = (i0 == 0) ? 1 : 0;
        #pragma unroll
        for (int i = 0; i < NE; i++) if (i != i0 && p[i] > p[i1]) i1 = i;

        g_sel[2*b]   = i0;
        g_sel[2*b+1] = i1;
        if (out_size >= OUT_ELEMS + 2*NROWS) {
            dout[OUT_ELEMS + 2*b]         = p[i0];
            dout[OUT_ELEMS + 2*b + 1]     = p[i1];
            dout[OUT_ELEMS + NROWS + 2*b]     = (float)i0;
            dout[OUT_ELEMS + NROWS + 2*b + 1] = (float)i1;
        }
    }
}

// ---------------- kernel 3: group rows by expert, build M-tile list --------
__global__ void group_kernel() {
    if (threadIdx.x != 0 || blockIdx.x != 0) return;
    int pos = 0, tiles = 0;
    for (int e = 0; e < NE; e++) {
        int start = pos;
        for (int n = 0; n < NROWS; n++)
            if (g_sel[n] == e) g_perm[pos++] = n;
        int cnt = pos - start;
        for (int r = 0; r < cnt; r += 4) {
            g_tile_e[tiles]    = e;
            g_tile_p0[tiles]   = start + r;
            g_tile_rows[tiles] = min(4, cnt - r);
            tiles++;
        }
    }
    g_ntiles = tiles;
}

// ---------------- FFN GEMMs: 128x128x16 fp32 SGEMM, 8x8 microtiles ---------
// PHASE 1: h = gelu(X @ W1[e] + b1[e])   K=768,  N=3072, A gathered via perm
// PHASE 2: out = h @ W2[e] + b2[e]       K=3072, N=768,  A contiguous (grouped)
template<int PHASE>
__launch_bounds__(256, 2)
__global__ void ffn_gemm(const float* __restrict__ X,
                         const float* __restrict__ W1,
                         const float* __restrict__ b1,
                         const float* __restrict__ W2,
                         const float* __restrict__ b2,
                         float* __restrict__ out) {
    const int mt = blockIdx.x;
    if (mt >= g_ntiles) return;
    const int e     = g_tile_e[mt];
    const int p0    = g_tile_p0[mt];
    const int nrows = g_tile_rows[mt];
    const int K = (PHASE == 1) ? D : DFF;
    const int N = (PHASE == 1) ? DFF : D;
    const float* __restrict__ B = (PHASE == 1) ? (W1 + (size_t)e*D*DFF)
                                               : (W2 + (size_t)e*DFF*D);
    const int jbase = blockIdx.y * 128;
    const int tid = threadIdx.x;

    __shared__ float As[16][128];
    __shared__ float Bs[16][128];

    // A loader assignment: each thread loads 8 floats of one row
    const int row_m = tid >> 1;
    const int koff  = (tid & 1) * 8;
    const bool avalid = (row_m >> 5) < nrows;
    const float* arow;
    if (PHASE == 1) {
        int n = avalid ? g_perm[p0 + (row_m >> 5)] : 0;
        arow = X + ((size_t)(n >> 1) * T + (row_m & 31)) * D;
    } else {
        arow = g_h + (size_t)(p0 * T + row_m) * DFF;
    }
    // B loader assignment
    const int brow = tid >> 4;
    const int bcol = (tid & 15) * 8;
    const float* bbase = B + (size_t)brow * N + jbase + bcol;

    const int tm = (tid >> 4) * 8;
    const int tn = (tid & 15) * 8;

    float acc[8][8];
    #pragma unroll
    for (int i = 0; i < 8; i++)
        #pragma unroll
        for (int j = 0; j < 8; j++) acc[i][j] = 0.f;

    for (int k0 = 0; k0 < K; k0 += 16) {
        float4 a0 = make_float4(0.f,0.f,0.f,0.f), a1 = a0;
        if (avalid) {
            a0 = *(const float4*)(arow + k0 + koff);
            a1 = *(const float4*)(arow + k0 + koff + 4);
        }
        const float* bp = bbase + (size_t)k0 * N;
        float4 bv0 = *(const float4*)(bp);
        float4 bv1 = *(const float4*)(bp + 4);

        __syncthreads();
        As[koff+0][row_m] = a0.x; As[koff+1][row_m] = a0.y;
        As[koff+2][row_m] = a0.z; As[koff+3][row_m] = a0.w;
        As[koff+4][row_m] = a1.x; As[koff+5][row_m] = a1.y;
        As[koff+6][row_m] = a1.z; As[koff+7][row_m] = a1.w;
        *(float4*)&Bs[brow][bcol]     = bv0;
        *(float4*)&Bs[brow][bcol + 4] = bv1;
        __syncthreads();

        #pragma unroll
        for (int kk = 0; kk < 16; kk++) {
            float4 ar0 = *(const float4*)&As[kk][tm];
            float4 ar1 = *(const float4*)&As[kk][tm + 4];
            float4 br0 = *(const float4*)&Bs[kk][tn];
            float4 br1 = *(const float4*)&Bs[kk][tn + 4];
            float a[8] = {ar0.x, ar0.y, ar0.z, ar0.w, ar1.x, ar1.y, ar1.z, ar1.w};
            float bb[8] = {br0.x, br0.y, br0.z, br0.w, br1.x, br1.y, br1.z, br1.w};
            #pragma unroll
            for (int i = 0; i < 8; i++)
                #pragma unroll
                for (int j = 0; j < 8; j++)
                    acc[i][j] = fmaf(a[i], bb[j], acc[i][j]);
        }
    }

    #pragma unroll
    for (int i = 0; i < 8; i++) {
        int m = tm + i;
        if ((m >> 5) >= nrows) continue;
        if (PHASE == 1) {
            size_t base = (size_t)(p0 * T + m) * DFF + jbase + tn;
            #pragma unroll
            for (int j = 0; j < 8; j++) {
                float v = acc[i][j] + b1[e*DFF + jbase + tn + j];
                g_h[base + j] = gelu_exact(v);
            }
        } else {
            int n = g_perm[p0 + (m >> 5)];
            size_t base = (size_t)(n * T + (m & 31)) * D + jbase + tn;
            #pragma unroll
            for (int j = 0; j < 8; j++)
                out[base + j] = acc[i][j] + b2[e*D + jbase + tn + j];
        }
    }
}

// ---------------- launch ----------------------------------------------------
extern "C" void kernel_launch(void* const* d_in, const int* in_sizes, int n_in,
                              void* d_out, int out_size) {
    const float* x  = (const float*)d_in[0];
    // d_in[1] = attention_mask (reference ignores it; all-ones)
    const float* Wg = (const float*)d_in[2];
    const float* W1 = (const float*)d_in[3];
    const float* b1 = (const float*)d_in[4];
    const float* W2 = (const float*)d_in[5];
    const float* b2 = (const float*)d_in[6];
    float* out = (float*)d_out;

    avg_kernel<<<BZ, 256>>>(x);
    router_kernel<<<BZ, 32>>>(Wg, out, out_size);
    group_kernel<<<1, 1>>>();
    ffn_gemm<1><<<dim3(MAX_TILES, DFF/128), 256>>>(x, W1, b1, W2, b2, out);
    ffn_gemm<2><<<dim3(MAX_TILES, D/128),  256>>>(x, W1, b1, W2, b2, out);
}

// round 4
// speedup vs baseline: 2.3070x; 2.3070x over previous
#include <cuda_runtime.h>
#include <math.h>
#include <stdint.h>

#define BZ   128
#define T    32
#define D    768
#define DFF  3072
#define NE   8
#define NROWS 256
#define OUT_ELEMS (NROWS*T*D)
#define MAX_TILES 72

#define KC   32                    // K chunk
#define AS_STRIDE 36               // floats per A smem row (conflict-free)
#define BS_STRIDE 136              // floats per B smem row (conflict-free)
#define A_STAGE (128*AS_STRIDE)    // 4608 floats
#define B_STAGE (32*BS_STRIDE)     // 4352 floats
#define SMEM_FLOATS ((A_STAGE + B_STAGE)*2)
#define SMEM_BYTES  (SMEM_FLOATS*4)   // 71680

// ---------------- scratch ---------------------------------------------------
__device__ float g_xavg[BZ*D];
__device__ int   g_sel[NROWS];
__device__ int   g_perm[NROWS];
__device__ int   g_tile_e[MAX_TILES];
__device__ int   g_tile_p0[MAX_TILES];
__device__ int   g_tile_rows[MAX_TILES];
__device__ int   g_ntiles;
__device__ float g_h[(size_t)NROWS*T*DFF];   // ~100 MB intermediate, grouped order

__device__ __forceinline__ float gelu_exact(float v) {
    return 0.5f * v * (1.0f + erff(v * 0.70710678118654752f));
}
__device__ __forceinline__ uint32_t cvt_tf32(float f) {
    uint32_t u;
    asm("cvt.rna.tf32.f32 %0, %1;" : "=r"(u) : "f"(f));
    return u;
}
__device__ __forceinline__ void mma_tf32(float* c,
                                         uint32_t a0, uint32_t a1, uint32_t a2, uint32_t a3,
                                         uint32_t b0, uint32_t b1) {
    asm volatile(
        "mma.sync.aligned.m16n8k8.row.col.f32.tf32.tf32.f32 "
        "{%0,%1,%2,%3}, {%4,%5,%6,%7}, {%8,%9}, {%0,%1,%2,%3};"
        : "+f"(c[0]), "+f"(c[1]), "+f"(c[2]), "+f"(c[3])
        : "r"(a0), "r"(a1), "r"(a2), "r"(a3), "r"(b0), "r"(b1));
}

// ---------------- kernel 1: x_avg -------------------------------------------
__global__ void avg_kernel(const float* __restrict__ x) {
    int b = blockIdx.x;
    for (int d = threadIdx.x; d < D; d += blockDim.x) {
        float s = 0.f;
        #pragma unroll
        for (int t = 0; t < T; t++) s += x[((size_t)b*T + t)*D + d];
        g_xavg[b*D + d] = s * (1.0f / T);
    }
}

// ---------------- kernel 2: router ------------------------------------------
__global__ void router_kernel(const float* __restrict__ Wg,
                              float* __restrict__ dout, int out_size) {
    int b = blockIdx.x;
    int lane = threadIdx.x;
    int e = lane & 7;
    int chunk = lane >> 3;
    float part = 0.f;
    const float* xa = g_xavg + b*D;
    for (int d = chunk*192; d < (chunk+1)*192; d++) part += xa[d] * Wg[d*NE + e];
    part += __shfl_down_sync(0xffffffffu, part, 16);
    part += __shfl_down_sync(0xffffffffu, part, 8);
    float lv[NE];
    #pragma unroll
    for (int i = 0; i < NE; i++) lv[i] = __shfl_sync(0xffffffffu, part, i);

    if (lane == 0) {
        float mx = lv[0];
        #pragma unroll
        for (int i = 1; i < NE; i++) mx = fmaxf(mx, lv[i]);
        float p[NE]; float sum = 0.f;
        #pragma unroll
        for (int i = 0; i < NE; i++) { p[i] = __expf(lv[i] - mx); sum += p[i]; }
        float inv = 1.0f / sum;
        #pragma unroll
        for (int i = 0; i < NE; i++) p[i] *= inv;
        int i0 = 0;
        #pragma unroll
        for (int i = 1; i < NE; i++) if (p[i] > p[i0]) i0 = i;
        int i1 = (i0 == 0) ? 1 : 0;
        #pragma unroll
        for (int i = 0; i < NE; i++) if (i != i0 && p[i] > p[i1]) i1 = i;
        g_sel[2*b] = i0; g_sel[2*b+1] = i1;
        if (out_size >= OUT_ELEMS + 2*NROWS) {
            dout[OUT_ELEMS + 2*b]             = p[i0];
            dout[OUT_ELEMS + 2*b + 1]         = p[i1];
            dout[OUT_ELEMS + NROWS + 2*b]     = (float)i0;
            dout[OUT_ELEMS + NROWS + 2*b + 1] = (float)i1;
        }
    }
}

// ---------------- kernel 3: group rows by expert ----------------------------
__global__ void group_kernel() {
    if (threadIdx.x != 0 || blockIdx.x != 0) return;
    int pos = 0, tiles = 0;
    for (int e = 0; e < NE; e++) {
        int start = pos;
        for (int n = 0; n < NROWS; n++) if (g_sel[n] == e) g_perm[pos++] = n;
        int cnt = pos - start;
        for (int r = 0; r < cnt; r += 4) {
            g_tile_e[tiles] = e; g_tile_p0[tiles] = start + r;
            g_tile_rows[tiles] = min(4, cnt - r); tiles++;
        }
    }
    g_ntiles = tiles;
}

// ---------------- tf32 mma.sync GEMM ----------------------------------------
// PHASE 1: g_h = gelu(X_perm @ W1[e] + b1[e]);  K=768,  N=3072
// PHASE 2: out[perm] = g_h @ W2[e] + b2[e];     K=3072, N=768
// CTA 128x128, 8 warps (2 m x 4 n), warp tile 64x32, m16n8k8 tf32.
template<int PHASE>
__global__ __launch_bounds__(256, 1) void ffn_mma(
    const float* __restrict__ X,
    const float* __restrict__ W1, const float* __restrict__ b1,
    const float* __restrict__ W2, const float* __restrict__ b2,
    float* __restrict__ out)
{
    const int mt = blockIdx.x;
    if (mt >= g_ntiles) return;
    const int e     = g_tile_e[mt];
    const int p0    = g_tile_p0[mt];
    const int nrows = g_tile_rows[mt];
    const int K  = (PHASE == 1) ? D : DFF;
    const int NF = (PHASE == 1) ? DFF : D;
    const float* __restrict__ Bsrc = (PHASE == 1) ? (W1 + (size_t)e*D*DFF)
                                                  : (W2 + (size_t)e*DFF*D);
    const int n0 = blockIdx.y * 128;
    const int NC = K / KC;
    const int tid = threadIdx.x, wid = tid >> 5, lane = tid & 31;

    extern __shared__ float smf[];
    float* A0 = smf;
    float* A1 = A0 + A_STAGE;
    float* B0 = A1 + A_STAGE;
    float* B1 = B0 + B_STAGE;

    // ---- loader assignment ----
    const int am   = tid >> 1;          // A row 0..127
    const int ah   = tid & 1;           // which 16-float half
    const int bk   = tid >> 3;          // B k-row 0..31
    const int bseg = tid & 7;           // B 16B segment

    const float* aptr;                  // global A row base (K-contiguous)
    {
        // Clamp invalid beam-rows into the valid region (values unused; the
        // epilogue masks them). Without this, last-tile reads run past g_h.
        int r = (am >> 5 < nrows) ? am : (am & 31);
        if (PHASE == 1) {
            int n = g_perm[p0 + (r >> 5)];
            aptr = X + ((size_t)(n >> 1)*T + (r & 31)) * (size_t)D;
        } else {
            aptr = g_h + ((size_t)(p0*T + r)) * (size_t)DFF;
        }
    }
    const float* bptr = Bsrc + (size_t)bk*NF + n0 + 4*bseg;

    // ---- mma fragment bases ----
    const int wm = (wid & 1) * 64;
    const int wn = (wid >> 1) * 32;
    const int g  = lane >> 2;
    const int t  = lane & 3;
    const float* Ab0 = A0 + (wm + g)*AS_STRIDE + t;
    const float* Ab1 = A1 + (wm + g)*AS_STRIDE + t;
    const float* Bb0 = B0 + t*BS_STRIDE + wn + g;
    const float* Bb1 = B1 + t*BS_STRIDE + wn + g;

    float acc[4][4][4];
    #pragma unroll
    for (int i = 0; i < 4; i++)
        #pragma unroll
        for (int j = 0; j < 4; j++)
            #pragma unroll
            for (int q = 0; q < 4; q++) acc[i][j][q] = 0.f;

    float4 sa[4], sb[4];

    #define LDG_CHUNK(k0) do {                                                \
        _Pragma("unroll")                                                     \
        for (int i = 0; i < 4; i++)                                           \
            sa[i] = *(const float4*)(aptr + (k0) + ah*16 + 4*i);              \
        _Pragma("unroll")                                                     \
        for (int i = 0; i < 4; i++)                                           \
            sb[i] = *(const float4*)(bptr + (size_t)(k0)*NF + 32*i);          \
    } while (0)

    #define STS_CHUNK(Ad, Bd) do {                                           \
        _Pragma("unroll")                                                     \
        for (int i = 0; i < 4; i++) {                                         \
            uint4 v = make_uint4(cvt_tf32(sa[i].x), cvt_tf32(sa[i].y),        \
                                 cvt_tf32(sa[i].z), cvt_tf32(sa[i].w));       \
            *(uint4*)((Ad) + am*AS_STRIDE + ah*16 + 4*i) = v;                 \
        }                                                                     \
        _Pragma("unroll")                                                     \
        for (int i = 0; i < 4; i++) {                                         \
            uint4 v = make_uint4(cvt_tf32(sb[i].x), cvt_tf32(sb[i].y),        \
                                 cvt_tf32(sb[i].z), cvt_tf32(sb[i].w));       \
            *(uint4*)((Bd) + bk*BS_STRIDE + 4*bseg + 32*i) = v;               \
        }                                                                     \
    } while (0)

    #define CONSUME(Ab, Bb) do {                                              \
        _Pragma("unroll")                                                     \
        for (int ks = 0; ks < 4; ks++) {                                      \
            uint32_t af[4][4], bf[4][2];                                      \
            _Pragma("unroll")                                                 \
            for (int mi = 0; mi < 4; mi++) {                                  \
                af[mi][0] = __float_as_uint((Ab)[mi*16*AS_STRIDE + ks*8]);    \
                af[mi][1] = __float_as_uint((Ab)[mi*16*AS_STRIDE + ks*8 + 8*AS_STRIDE]); \
                af[mi][2] = __float_as_uint((Ab)[mi*16*AS_STRIDE + ks*8 + 4]);\
                af[mi][3] = __float_as_uint((Ab)[mi*16*AS_STRIDE + ks*8 + 8*AS_STRIDE + 4]); \
            }                                                                 \
            _Pragma("unroll")                                                 \
            for (int ni = 0; ni < 4; ni++) {                                  \
                bf[ni][0] = __float_as_uint((Bb)[ks*8*BS_STRIDE + ni*8]);     \
                bf[ni][1] = __float_as_uint((Bb)[ks*8*BS_STRIDE + ni*8 + 4*BS_STRIDE]); \
            }                                                                 \
            _Pragma("unroll")                                                 \
            for (int mi = 0; mi < 4; mi++)                                    \
                _Pragma("unroll")                                             \
                for (int ni = 0; ni < 4; ni++)                                \
                    mma_tf32(acc[mi][ni], af[mi][0], af[mi][1], af[mi][2],    \
                             af[mi][3], bf[ni][0], bf[ni][1]);                \
        }                                                                     \
    } while (0)

    // ---- prologue ----
    LDG_CHUNK(0);
    STS_CHUNK(A0, B0);
    __syncthreads();

    // ---- main loop: double-buffered, one barrier per chunk ----
    for (int c = 0; c < NC; c++) {
        const bool more = (c + 1 < NC);
        if (more) LDG_CHUNK((c + 1) * KC);
        if (c & 1) CONSUME(Ab1, Bb1);
        else       CONSUME(Ab0, Bb0);
        if (more) {
            if (c & 1) STS_CHUNK(A0, B0);
            else       STS_CHUNK(A1, B1);
        }
        __syncthreads();
    }

    // ---- epilogue: bias (+gelu) and store ----
    const float* bias = (PHASE == 1) ? (b1 + e*DFF + n0) : (b2 + e*D + n0);
    #pragma unroll
    for (int mi = 0; mi < 4; mi++) {
        #pragma unroll
        for (int h = 0; h < 2; h++) {
            int r = wm + 16*mi + g + 8*h;
            int br = r >> 5;
            if (br >= nrows) continue;
            float* dst;
            if (PHASE == 1) {
                dst = g_h + ((size_t)(p0*T + r)) * (size_t)DFF + n0;
            } else {
                int n = g_perm[p0 + br];
                dst = out + ((size_t)n*T + (r & 31)) * (size_t)D + n0;
            }
            #pragma unroll
            for (int ni = 0; ni < 4; ni++) {
                int col = wn + 8*ni + 2*t;
                float v0 = acc[mi][ni][2*h + 0] + bias[col];
                float v1 = acc[mi][ni][2*h + 1] + bias[col + 1];
                if (PHASE == 1) { v0 = gelu_exact(v0); v1 = gelu_exact(v1); }
                *(float2*)(dst + col) = make_float2(v0, v1);
            }
        }
    }
    #undef LDG_CHUNK
    #undef STS_CHUNK
    #undef CONSUME
}

// ---------------- launch ----------------------------------------------------
extern "C" void kernel_launch(void* const* d_in, const int* in_sizes, int n_in,
                              void* d_out, int out_size) {
    const float* x  = (const float*)d_in[0];
    const float* Wg = (const float*)d_in[2];
    const float* W1 = (const float*)d_in[3];
    const float* b1 = (const float*)d_in[4];
    const float* W2 = (const float*)d_in[5];
    const float* b2 = (const float*)d_in[6];
    float* out = (float*)d_out;

    cudaFuncSetAttribute(ffn_mma<1>, cudaFuncAttributeMaxDynamicSharedMemorySize, SMEM_BYTES);
    cudaFuncSetAttribute(ffn_mma<2>, cudaFuncAttributeMaxDynamicSharedMemorySize, SMEM_BYTES);

    avg_kernel<<<BZ, 256>>>(x);
    router_kernel<<<BZ, 32>>>(Wg, out, out_size);
    group_kernel<<<1, 1>>>();
    ffn_mma<1><<<dim3(MAX_TILES, DFF/128), 256, SMEM_BYTES>>>(x, W1, b1, W2, b2, out);
    ffn_mma<2><<<dim3(MAX_TILES, D/128),  256, SMEM_BYTES>>>(x, W1, b1, W2, b2, out);
}

// round 5
// speedup vs baseline: 2.4824x; 1.0760x over previous
#include <cuda_runtime.h>
#include <math.h>
#include <stdint.h>

#define BZ   128
#define T    32
#define D    768
#define DFF  3072
#define NE   8
#define NROWS 256
#define OUT_ELEMS (NROWS*T*D)
#define MAX_TILES 72

#define NT        256                 // CTA N tile
#define KC        32                  // K chunk
#define STAGES    3
#define AS_STRIDE 36                  // floats per A smem row
#define BS_STRIDE 264                 // floats per B smem k-row
#define A_STAGE   (128*AS_STRIDE)     // 4608 floats
#define B_STAGE   (KC*BS_STRIDE)      // 8448 floats
#define STAGE_FLOATS (A_STAGE + B_STAGE)       // 13056
#define SMEM_BYTES   (STAGES*STAGE_FLOATS*4)   // 156672

// ---------------- scratch ---------------------------------------------------
__device__ float g_xavg[BZ*D];
__device__ int   g_sel[NROWS];
__device__ int   g_perm[NROWS];
__device__ int   g_tile_e[MAX_TILES];
__device__ int   g_tile_p0[MAX_TILES];
__device__ int   g_tile_rows[MAX_TILES];
__device__ int   g_ntiles;
__device__ float g_h[(size_t)NROWS*T*DFF];   // ~100 MB intermediate, grouped order

__device__ __forceinline__ float gelu_exact(float v) {
    return 0.5f * v * (1.0f + erff(v * 0.70710678118654752f));
}
__device__ __forceinline__ uint32_t cvt_tf32(float f) {
    uint32_t u;
    asm("cvt.rna.tf32.f32 %0, %1;" : "=r"(u) : "f"(f));
    return u;
}
__device__ __forceinline__ void mma_tf32(float* c,
                                         uint32_t a0, uint32_t a1, uint32_t a2, uint32_t a3,
                                         uint32_t b0, uint32_t b1) {
    asm volatile(
        "mma.sync.aligned.m16n8k8.row.col.f32.tf32.tf32.f32 "
        "{%0,%1,%2,%3}, {%4,%5,%6,%7}, {%8,%9}, {%0,%1,%2,%3};"
        : "+f"(c[0]), "+f"(c[1]), "+f"(c[2]), "+f"(c[3])
        : "r"(a0), "r"(a1), "r"(a2), "r"(a3), "r"(b0), "r"(b1));
}
__device__ __forceinline__ void cp16(uint32_t saddr, const void* g) {
    asm volatile("cp.async.cg.shared.global [%0], [%1], 16;" :: "r"(saddr), "l"(g));
}

// ---------------- kernel 1: x_avg -------------------------------------------
__global__ void avg_kernel(const float* __restrict__ x) {
    int b = blockIdx.x;
    for (int d = threadIdx.x; d < D; d += blockDim.x) {
        float s = 0.f;
        #pragma unroll
        for (int t = 0; t < T; t++) s += x[((size_t)b*T + t)*D + d];
        g_xavg[b*D + d] = s * (1.0f / T);
    }
}

// ---------------- kernel 2: router ------------------------------------------
__global__ void router_kernel(const float* __restrict__ Wg,
                              float* __restrict__ dout, int out_size) {
    int b = blockIdx.x;
    int lane = threadIdx.x;
    int e = lane & 7;
    int chunk = lane >> 3;
    float part = 0.f;
    const float* xa = g_xavg + b*D;
    for (int d = chunk*192; d < (chunk+1)*192; d++) part += xa[d] * Wg[d*NE + e];
    part += __shfl_down_sync(0xffffffffu, part, 16);
    part += __shfl_down_sync(0xffffffffu, part, 8);
    float lv[NE];
    #pragma unroll
    for (int i = 0; i < NE; i++) lv[i] = __shfl_sync(0xffffffffu, part, i);

    if (lane == 0) {
        float mx = lv[0];
        #pragma unroll
        for (int i = 1; i < NE; i++) mx = fmaxf(mx, lv[i]);
        float p[NE]; float sum = 0.f;
        #pragma unroll
        for (int i = 0; i < NE; i++) { p[i] = __expf(lv[i] - mx); sum += p[i]; }
        float inv = 1.0f / sum;
        #pragma unroll
        for (int i = 0; i < NE; i++) p[i] *= inv;
        int i0 = 0;
        #pragma unroll
        for (int i = 1; i < NE; i++) if (p[i] > p[i0]) i0 = i;
        int i1 = (i0 == 0) ? 1 : 0;
        #pragma unroll
        for (int i = 0; i < NE; i++) if (i != i0 && p[i] > p[i1]) i1 = i;
        g_sel[2*b] = i0; g_sel[2*b+1] = i1;
        if (out_size >= OUT_ELEMS + 2*NROWS) {
            dout[OUT_ELEMS + 2*b]             = p[i0];
            dout[OUT_ELEMS + 2*b + 1]         = p[i1];
            dout[OUT_ELEMS + NROWS + 2*b]     = (float)i0;
            dout[OUT_ELEMS + NROWS + 2*b + 1] = (float)i1;
        }
    }
}

// ---------------- kernel 3: group rows by expert ----------------------------
__global__ void group_kernel() {
    if (threadIdx.x != 0 || blockIdx.x != 0) return;
    int pos = 0, tiles = 0;
    for (int e = 0; e < NE; e++) {
        int start = pos;
        for (int n = 0; n < NROWS; n++) if (g_sel[n] == e) g_perm[pos++] = n;
        int cnt = pos - start;
        for (int r = 0; r < cnt; r += 4) {
            g_tile_e[tiles] = e; g_tile_p0[tiles] = start + r;
            g_tile_rows[tiles] = min(4, cnt - r); tiles++;
        }
    }
    g_ntiles = tiles;
}

// ---------------- tf32 mma.sync GEMM, cp.async 3-stage ----------------------
// PHASE 1: g_h = gelu(X_perm @ W1[e] + b1[e]);  K=768,  N=3072
// PHASE 2: out[perm] = g_h @ W2[e] + b2[e];     K=3072, N=768
// CTA 128x256, 512 threads / 16 warps (2 m x 8 n), warp tile 64x32.
template<int PHASE>
__global__ __launch_bounds__(512, 1) void ffn_mma(
    const float* __restrict__ X,
    const float* __restrict__ W1, const float* __restrict__ b1,
    const float* __restrict__ W2, const float* __restrict__ b2,
    float* __restrict__ out)
{
    const int mt = blockIdx.x;
    if (mt >= g_ntiles) return;
    const int e     = g_tile_e[mt];
    const int p0    = g_tile_p0[mt];
    const int nrows = g_tile_rows[mt];
    const int K  = (PHASE == 1) ? D : DFF;
    const int NF = (PHASE == 1) ? DFF : D;
    const float* __restrict__ Bsrc = (PHASE == 1) ? (W1 + (size_t)e*D*DFF)
                                                  : (W2 + (size_t)e*DFF*D);
    const int n0 = blockIdx.y * NT;
    const int NC = K / KC;
    const int tid = threadIdx.x, wid = tid >> 5, lane = tid & 31;

    extern __shared__ float smf[];

    // ---- async loader assignment ----
    // A: 128 rows x 32 floats; thread -> row tid>>2, seg tid&3 (2x cp16)
    // B: 32 k-rows x 256 floats; thread -> row tid>>4, seg tid&15 (4x cp16)
    const int arow = tid >> 2, aseg = tid & 3;
    const int brow = tid >> 4, bseg = tid & 15;

    const float* aglob;     // base of this thread's A row in gmem (K-contig)
    {
        int r = ((arow >> 5) < nrows) ? arow : (arow & 31);  // clamp pad rows
        if (PHASE == 1) {
            int n = g_perm[p0 + (r >> 5)];
            aglob = X + ((size_t)(n >> 1)*T + (r & 31)) * (size_t)D;
        } else {
            aglob = g_h + ((size_t)(p0*T + r)) * (size_t)DFF;
        }
    }
    const float* bglob = Bsrc + (size_t)brow*NF + n0;

    uint32_t sbase = (uint32_t)__cvta_generic_to_shared(smf);
    uint32_t aSts[STAGES], bSts[STAGES];
    #pragma unroll
    for (int s = 0; s < STAGES; s++) {
        aSts[s] = sbase + (s*STAGE_FLOATS + arow*AS_STRIDE)*4;
        bSts[s] = sbase + (s*STAGE_FLOATS + A_STAGE + brow*BS_STRIDE)*4;
    }

    #define ISSUE(k0, s) do {                                                 \
        _Pragma("unroll")                                                     \
        for (int i = 0; i < 2; i++)                                           \
            cp16(aSts[s] + (aseg + 4*i)*16, aglob + (k0) + (aseg + 4*i)*4);   \
        _Pragma("unroll")                                                     \
        for (int i = 0; i < 4; i++)                                           \
            cp16(bSts[s] + (bseg + 16*i)*16,                                  \
                 bglob + (size_t)(k0)*NF + (bseg + 16*i)*4);                  \
    } while (0)

    // ---- mma fragment bases (per stage) ----
    const int wm = (wid & 1) * 64;
    const int wn = (wid >> 1) * 32;
    const int g  = lane >> 2;
    const int t  = lane & 3;
    const float* Abf[STAGES];
    const float* Bbf[STAGES];
    #pragma unroll
    for (int s = 0; s < STAGES; s++) {
        Abf[s] = smf + s*STAGE_FLOATS + (wm + g)*AS_STRIDE + t;
        Bbf[s] = smf + s*STAGE_FLOATS + A_STAGE + t*BS_STRIDE + wn + g;
    }

    float acc[4][4][4];
    #pragma unroll
    for (int i = 0; i < 4; i++)
        #pragma unroll
        for (int j = 0; j < 4; j++)
            #pragma unroll
            for (int q = 0; q < 4; q++) acc[i][j][q] = 0.f;

    #define CONSUME(Ab, Bb) do {                                              \
        _Pragma("unroll")                                                     \
        for (int ks = 0; ks < 4; ks++) {                                      \
            uint32_t af[4][4], bf[4][2];                                      \
            _Pragma("unroll")                                                 \
            for (int mi = 0; mi < 4; mi++) {                                  \
                af[mi][0] = cvt_tf32((Ab)[mi*16*AS_STRIDE + ks*8]);           \
                af[mi][1] = cvt_tf32((Ab)[mi*16*AS_STRIDE + ks*8 + 8*AS_STRIDE]); \
                af[mi][2] = cvt_tf32((Ab)[mi*16*AS_STRIDE + ks*8 + 4]);       \
                af[mi][3] = cvt_tf32((Ab)[mi*16*AS_STRIDE + ks*8 + 8*AS_STRIDE + 4]); \
            }                                                                 \
            _Pragma("unroll")                                                 \
            for (int ni = 0; ni < 4; ni++) {                                  \
                bf[ni][0] = cvt_tf32((Bb)[ks*8*BS_STRIDE + ni*8]);            \
                bf[ni][1] = cvt_tf32((Bb)[ks*8*BS_STRIDE + ni*8 + 4*BS_STRIDE]); \
            }                                                                 \
            _Pragma("unroll")                                                 \
            for (int mi = 0; mi < 4; mi++)                                    \
                _Pragma("unroll")                                             \
                for (int ni = 0; ni < 4; ni++)                                \
                    mma_tf32(acc[mi][ni], af[mi][0], af[mi][1], af[mi][2],    \
                             af[mi][3], bf[ni][0], bf[ni][1]);                \
        }                                                                     \
    } while (0)

    // ---- prologue: chunks 0,1 in flight ----
    ISSUE(0, 0);
    asm volatile("cp.async.commit_group;" ::: "memory");
    ISSUE(KC, 1);
    asm volatile("cp.async.commit_group;" ::: "memory");

    // ---- main loop ----
    for (int c = 0; c < NC; c++) {
        if (c + 2 < NC) ISSUE((c + 2)*KC, (c + 2) % STAGES);
        asm volatile("cp.async.commit_group;" ::: "memory");
        asm volatile("cp.async.wait_group 1;" ::: "memory");
        __syncthreads();                       // chunk c visible to all
        switch (c % STAGES) {
            case 0: CONSUME(Abf[0], Bbf[0]); break;
            case 1: CONSUME(Abf[1], Bbf[1]); break;
            default: CONSUME(Abf[2], Bbf[2]); break;
        }
        __syncthreads();                       // all done reading stage c%3
    }

    // ---- epilogue: bias (+gelu) and store ----
    const float* bias = (PHASE == 1) ? (b1 + e*DFF + n0) : (b2 + e*D + n0);
    #pragma unroll
    for (int mi = 0; mi < 4; mi++) {
        #pragma unroll
        for (int h = 0; h < 2; h++) {
            int r = wm + 16*mi + g + 8*h;
            int br = r >> 5;
            if (br >= nrows) continue;
            float* dst;
            if (PHASE == 1) {
                dst = g_h + ((size_t)(p0*T + r)) * (size_t)DFF + n0;
            } else {
                int n = g_perm[p0 + br];
                dst = out + ((size_t)n*T + (r & 31)) * (size_t)D + n0;
            }
            #pragma unroll
            for (int ni = 0; ni < 4; ni++) {
                int col = wn + 8*ni + 2*t;
                float v0 = acc[mi][ni][2*h + 0] + bias[col];
                float v1 = acc[mi][ni][2*h + 1] + bias[col + 1];
                if (PHASE == 1) { v0 = gelu_exact(v0); v1 = gelu_exact(v1); }
                *(float2*)(dst + col) = make_float2(v0, v1);
            }
        }
    }
    #undef ISSUE
    #undef CONSUME
}

// ---------------- launch ----------------------------------------------------
extern "C" void kernel_launch(void* const* d_in, const int* in_sizes, int n_in,
                              void* d_out, int out_size) {
    const float* x  = (const float*)d_in[0];
    const float* Wg = (const float*)d_in[2];
    const float* W1 = (const float*)d_in[3];
    const float* b1 = (const float*)d_in[4];
    const float* W2 = (const float*)d_in[5];
    const float* b2 = (const float*)d_in[6];
    float* out = (float*)d_out;

    cudaFuncSetAttribute(ffn_mma<1>, cudaFuncAttributeMaxDynamicSharedMemorySize, SMEM_BYTES);
    cudaFuncSetAttribute(ffn_mma<2>, cudaFuncAttributeMaxDynamicSharedMemorySize, SMEM_BYTES);

    avg_kernel<<<BZ, 256>>>(x);
    router_kernel<<<BZ, 32>>>(Wg, out, out_size);
    group_kernel<<<1, 1>>>();
    ffn_mma<1><<<dim3(MAX_TILES, DFF/NT), 512, SMEM_BYTES>>>(x, W1, b1, W2, b2, out);
    ffn_mma<2><<<dim3(MAX_TILES, D/NT),  512, SMEM_BYTES>>>(x, W1, b1, W2, b2, out);
}

// round 6
// speedup vs baseline: 2.9527x; 1.1894x over previous
#include <cuda_runtime.h>
#include <math.h>
#include <stdint.h>

#define BZ   128
#define T    32
#define D    768
#define DFF  3072
#define NE   8
#define NROWS 256
#define OUT_ELEMS (NROWS*T*D)
#define MAX_TILES 72

#define NT        256                 // CTA N tile
#define KC        32                  // K chunk
#define STAGES    3
#define AS_STRIDE 36                  // floats per A smem row
#define BS_STRIDE 264                 // floats per B smem k-row
#define A_STAGE   (128*AS_STRIDE)     // 4608 floats
#define B_STAGE   (KC*BS_STRIDE)      // 8448 floats
#define STAGE_FLOATS (A_STAGE + B_STAGE)       // 13056
#define SMEM_BYTES   (STAGES*STAGE_FLOATS*4)   // 156672

// ---------------- scratch ---------------------------------------------------
__device__ float g_xavg[BZ*D];
__device__ int   g_sel[NROWS];
__device__ int   g_perm[NROWS];
__device__ int   g_tile_e[MAX_TILES];
__device__ int   g_tile_p0[MAX_TILES];
__device__ int   g_tile_rows[MAX_TILES];
__device__ int   g_ntiles;
__device__ float g_xr[(size_t)BZ*T*D];       // tf32-rounded copy of x
__device__ float g_h[(size_t)NROWS*T*DFF];   // intermediate (tf32-rounded), grouped

__device__ __forceinline__ float gelu_exact(float v) {
    return 0.5f * v * (1.0f + erff(v * 0.70710678118654752f));
}
__device__ __forceinline__ uint32_t cvt_tf32(float f) {
    uint32_t u;
    asm("cvt.rna.tf32.f32 %0, %1;" : "=r"(u) : "f"(f));
    return u;
}
__device__ __forceinline__ void mma_tf32(float* c,
                                         uint32_t a0, uint32_t a1, uint32_t a2, uint32_t a3,
                                         uint32_t b0, uint32_t b1) {
    asm volatile(
        "mma.sync.aligned.m16n8k8.row.col.f32.tf32.tf32.f32 "
        "{%0,%1,%2,%3}, {%4,%5,%6,%7}, {%8,%9}, {%0,%1,%2,%3};"
        : "+f"(c[0]), "+f"(c[1]), "+f"(c[2]), "+f"(c[3])
        : "r"(a0), "r"(a1), "r"(a2), "r"(a3), "r"(b0), "r"(b1));
}
__device__ __forceinline__ void cp16(uint32_t saddr, const void* g) {
    asm volatile("cp.async.cg.shared.global [%0], [%1], 16;" :: "r"(saddr), "l"(g));
}

// ---------------- kernel 0: tf32-round x ------------------------------------
__global__ void round_x_kernel(const float* __restrict__ x) {
    int i = blockIdx.x * blockDim.x + threadIdx.x;
    const int n4 = BZ*T*D/4;
    if (i < n4) {
        float4 v = ((const float4*)x)[i];
        uint4 r = make_uint4(cvt_tf32(v.x), cvt_tf32(v.y), cvt_tf32(v.z), cvt_tf32(v.w));
        ((uint4*)g_xr)[i] = r;
    }
}

// ---------------- kernel 1: x_avg (raw x, full precision) -------------------
__global__ void avg_kernel(const float* __restrict__ x) {
    int b = blockIdx.x;
    for (int d = threadIdx.x; d < D; d += blockDim.x) {
        float s = 0.f;
        #pragma unroll
        for (int t = 0; t < T; t++) s += x[((size_t)b*T + t)*D + d];
        g_xavg[b*D + d] = s * (1.0f / T);
    }
}

// ---------------- kernel 2: router ------------------------------------------
__global__ void router_kernel(const float* __restrict__ Wg,
                              float* __restrict__ dout, int out_size) {
    int b = blockIdx.x;
    int lane = threadIdx.x;
    int e = lane & 7;
    int chunk = lane >> 3;
    float part = 0.f;
    const float* xa = g_xavg + b*D;
    for (int d = chunk*192; d < (chunk+1)*192; d++) part += xa[d] * Wg[d*NE + e];
    part += __shfl_down_sync(0xffffffffu, part, 16);
    part += __shfl_down_sync(0xffffffffu, part, 8);
    float lv[NE];
    #pragma unroll
    for (int i = 0; i < NE; i++) lv[i] = __shfl_sync(0xffffffffu, part, i);

    if (lane == 0) {
        float mx = lv[0];
        #pragma unroll
        for (int i = 1; i < NE; i++) mx = fmaxf(mx, lv[i]);
        float p[NE]; float sum = 0.f;
        #pragma unroll
        for (int i = 0; i < NE; i++) { p[i] = __expf(lv[i] - mx); sum += p[i]; }
        float inv = 1.0f / sum;
        #pragma unroll
        for (int i = 0; i < NE; i++) p[i] *= inv;
        int i0 = 0;
        #pragma unroll
        for (int i = 1; i < NE; i++) if (p[i] > p[i0]) i0 = i;
        int i1 = (i0 == 0) ? 1 : 0;
        #pragma unroll
        for (int i = 0; i < NE; i++) if (i != i0 && p[i] > p[i1]) i1 = i;
        g_sel[2*b] = i0; g_sel[2*b+1] = i1;
        if (out_size >= OUT_ELEMS + 2*NROWS) {
            dout[OUT_ELEMS + 2*b]             = p[i0];
            dout[OUT_ELEMS + 2*b + 1]         = p[i1];
            dout[OUT_ELEMS + NROWS + 2*b]     = (float)i0;
            dout[OUT_ELEMS + NROWS + 2*b + 1] = (float)i1;
        }
    }
}

// ---------------- kernel 3: group rows by expert ----------------------------
__global__ void group_kernel() {
    if (threadIdx.x != 0 || blockIdx.x != 0) return;
    int pos = 0, tiles = 0;
    for (int e = 0; e < NE; e++) {
        int start = pos;
        for (int n = 0; n < NROWS; n++) if (g_sel[n] == e) g_perm[pos++] = n;
        int cnt = pos - start;
        for (int r = 0; r < cnt; r += 4) {
            g_tile_e[tiles] = e; g_tile_p0[tiles] = start + r;
            g_tile_rows[tiles] = min(4, cnt - r); tiles++;
        }
    }
    g_ntiles = tiles;
}

// ---------------- tf32 mma.sync GEMM, cp.async 3-stage ----------------------
// PHASE 1: g_h = round(gelu(Xr_perm @ W1[e] + b1[e]));  K=768,  N=3072
// PHASE 2 (split-K=2): out[perm] += g_h @ W2[e](+b2 on kp0); K=1536/part
// CTA 128x256, 512 threads / 16 warps (2m x 8n), warp tile 64x32.
template<int PHASE>
__global__ __launch_bounds__(512, 1) void ffn_mma(
    const float* __restrict__ X,
    const float* __restrict__ W1, const float* __restrict__ b1,
    const float* __restrict__ W2, const float* __restrict__ b2,
    float* __restrict__ out)
{
    const int mt = blockIdx.x;
    if (mt >= g_ntiles) return;
    const int e     = g_tile_e[mt];
    const int p0    = g_tile_p0[mt];
    const int nrows = g_tile_rows[mt];
    const int kp    = (PHASE == 2) ? blockIdx.z : 0;
    const int Ktot  = (PHASE == 1) ? D : DFF;
    const int NF    = (PHASE == 1) ? DFF : D;
    const int kbase = (PHASE == 2) ? kp * (DFF/2) : 0;
    const int NC    = ((PHASE == 1) ? Ktot : Ktot/2) / KC;
    const float* __restrict__ Bsrc = (PHASE == 1) ? (W1 + (size_t)e*D*DFF)
                                                  : (W2 + (size_t)e*DFF*D);
    const int n0 = blockIdx.y * NT;
    const int tid = threadIdx.x, wid = tid >> 5, lane = tid & 31;

    extern __shared__ float smf[];

    // ---- async loader assignment ----
    const int arow = tid >> 2, aseg = tid & 3;     // A: row, 16B seg (2x cp16)
    const int brow = tid >> 4, bseg = tid & 15;    // B: k-row, 16B seg (4x cp16)

    const float* aglob;
    {
        int r = ((arow >> 5) < nrows) ? arow : (arow & 31);  // clamp pad rows
        if (PHASE == 1) {
            int n = g_perm[p0 + (r >> 5)];
            aglob = g_xr + ((size_t)(n >> 1)*T + (r & 31)) * (size_t)D;
        } else {
            aglob = g_h + ((size_t)(p0*T + r)) * (size_t)DFF;
        }
    }
    const float* bglob = Bsrc + (size_t)brow*NF + n0;

    uint32_t sbase = (uint32_t)__cvta_generic_to_shared(smf);
    uint32_t aSts[STAGES], bSts[STAGES];
    #pragma unroll
    for (int s = 0; s < STAGES; s++) {
        aSts[s] = sbase + (s*STAGE_FLOATS + arow*AS_STRIDE)*4;
        bSts[s] = sbase + (s*STAGE_FLOATS + A_STAGE + brow*BS_STRIDE)*4;
    }

    #define ISSUE(k0, s) do {                                                 \
        _Pragma("unroll")                                                     \
        for (int i = 0; i < 2; i++)                                           \
            cp16(aSts[s] + (aseg + 4*i)*16, aglob + (k0) + (aseg + 4*i)*4);   \
        _Pragma("unroll")                                                     \
        for (int i = 0; i < 4; i++)                                           \
            cp16(bSts[s] + (bseg + 16*i)*16,                                  \
                 bglob + (size_t)(k0)*NF + (bseg + 16*i)*4);                  \
    } while (0)

    // ---- mma fragment bases (per stage) ----
    const int wm = (wid & 1) * 64;
    const int wn = (wid >> 1) * 32;
    const int g  = lane >> 2;
    const int t  = lane & 3;
    const float* Abf[STAGES];
    const float* Bbf[STAGES];
    #pragma unroll
    for (int s = 0; s < STAGES; s++) {
        Abf[s] = smf + s*STAGE_FLOATS + (wm + g)*AS_STRIDE + t;
        Bbf[s] = smf + s*STAGE_FLOATS + A_STAGE + t*BS_STRIDE + wn + g;
    }

    float acc[4][4][4];
    #pragma unroll
    for (int i = 0; i < 4; i++)
        #pragma unroll
        for (int j = 0; j < 4; j++)
            #pragma unroll
            for (int q = 0; q < 4; q++) acc[i][j][q] = 0.f;

    // A data is pre-rounded (g_xr / g_h stored rounded): raw bit reuse.
    #define CONSUME(Ab, Bb) do {                                              \
        _Pragma("unroll")                                                     \
        for (int ks = 0; ks < 4; ks++) {                                      \
            uint32_t af[4][4], bf[4][2];                                      \
            _Pragma("unroll")                                                 \
            for (int mi = 0; mi < 4; mi++) {                                  \
                af[mi][0] = __float_as_uint((Ab)[mi*16*AS_STRIDE + ks*8]);    \
                af[mi][1] = __float_as_uint((Ab)[mi*16*AS_STRIDE + ks*8 + 8*AS_STRIDE]); \
                af[mi][2] = __float_as_uint((Ab)[mi*16*AS_STRIDE + ks*8 + 4]);\
                af[mi][3] = __float_as_uint((Ab)[mi*16*AS_STRIDE + ks*8 + 8*AS_STRIDE + 4]); \
            }                                                                 \
            _Pragma("unroll")                                                 \
            for (int ni = 0; ni < 4; ni++) {                                  \
                bf[ni][0] = cvt_tf32((Bb)[ks*8*BS_STRIDE + ni*8]);            \
                bf[ni][1] = cvt_tf32((Bb)[ks*8*BS_STRIDE + ni*8 + 4*BS_STRIDE]); \
            }                                                                 \
            _Pragma("unroll")                                                 \
            for (int mi = 0; mi < 4; mi++)                                    \
                _Pragma("unroll")                                             \
                for (int ni = 0; ni < 4; ni++)                                \
                    mma_tf32(acc[mi][ni], af[mi][0], af[mi][1], af[mi][2],    \
                             af[mi][3], bf[ni][0], bf[ni][1]);                \
        }                                                                     \
    } while (0)

    // ---- prologue: chunks 0,1 in flight ----
    ISSUE(kbase, 0);
    asm volatile("cp.async.commit_group;" ::: "memory");
    ISSUE(kbase + KC, 1);
    asm volatile("cp.async.commit_group;" ::: "memory");

    // ---- main loop: single barrier per chunk ----
    for (int c = 0; c < NC; c++) {
        asm volatile("cp.async.wait_group 1;" ::: "memory");
        __syncthreads();                 // chunk c visible; consume(c-1) done
        if (c + 2 < NC) ISSUE(kbase + (c + 2)*KC, (c + 2) % STAGES);
        asm volatile("cp.async.commit_group;" ::: "memory");
        switch (c % STAGES) {
            case 0: CONSUME(Abf[0], Bbf[0]); break;
            case 1: CONSUME(Abf[1], Bbf[1]); break;
            default: CONSUME(Abf[2], Bbf[2]); break;
        }
    }

    // ---- epilogue ----
    const float* bias = (PHASE == 1) ? (b1 + e*DFF + n0) : (b2 + e*D + n0);
    #pragma unroll
    for (int mi = 0; mi < 4; mi++) {
        #pragma unroll
        for (int h = 0; h < 2; h++) {
            int r = wm + 16*mi + g + 8*h;
            int br = r >> 5;
            if (br >= nrows) continue;
            if (PHASE == 1) {
                float* dst = g_h + ((size_t)(p0*T + r)) * (size_t)DFF + n0;
                #pragma unroll
                for (int ni = 0; ni < 4; ni++) {
                    int col = wn + 8*ni + 2*t;
                    float v0 = gelu_exact(acc[mi][ni][2*h + 0] + bias[col]);
                    float v1 = gelu_exact(acc[mi][ni][2*h + 1] + bias[col + 1]);
                    // store tf32-pre-rounded so gemm2 skips A cvt
                    uint2 w = make_uint2(cvt_tf32(v0), cvt_tf32(v1));
                    *(uint2*)(dst + col) = w;
                }
            } else {
                int n = g_perm[p0 + br];
                float* dst = out + ((size_t)n*T + (r & 31)) * (size_t)D + n0;
                #pragma unroll
                for (int ni = 0; ni < 4; ni++) {
                    int col = wn + 8*ni + 2*t;
                    float v0 = acc[mi][ni][2*h + 0];
                    float v1 = acc[mi][ni][2*h + 1];
                    if (kp == 0) { v0 += bias[col]; v1 += bias[col + 1]; }
                    // exactly 2 atomic contributions per element onto 0-init:
                    // order-invariant -> deterministic
                    atomicAdd(dst + col,     v0);
                    atomicAdd(dst + col + 1, v1);
                }
            }
        }
    }
    #undef ISSUE
    #undef CONSUME
}

// ---------------- launch ----------------------------------------------------
extern "C" void kernel_launch(void* const* d_in, const int* in_sizes, int n_in,
                              void* d_out, int out_size) {
    const float* x  = (const float*)d_in[0];
    const float* Wg = (const float*)d_in[2];
    const float* W1 = (const float*)d_in[3];
    const float* b1 = (const float*)d_in[4];
    const float* W2 = (const float*)d_in[5];
    const float* b2 = (const float*)d_in[6];
    float* out = (float*)d_out;

    cudaFuncSetAttribute(ffn_mma<1>, cudaFuncAttributeMaxDynamicSharedMemorySize, SMEM_BYTES);
    cudaFuncSetAttribute(ffn_mma<2>, cudaFuncAttributeMaxDynamicSharedMemorySize, SMEM_BYTES);

    cudaMemsetAsync(out, 0, (size_t)out_size * sizeof(float));
    round_x_kernel<<<(BZ*T*D/4 + 255)/256, 256>>>(x);
    avg_kernel<<<BZ, 256>>>(x);
    router_kernel<<<BZ, 32>>>(Wg, out, out_size);
    group_kernel<<<1, 1>>>();
    ffn_mma<1><<<dim3(MAX_TILES, DFF/NT),    512, SMEM_BYTES>>>(x, W1, b1, W2, b2, out);
    ffn_mma<2><<<dim3(MAX_TILES, D/NT, 2),   512, SMEM_BYTES>>>(x, W1, b1, W2, b2, out);
}

// round 7
// speedup vs baseline: 3.1488x; 1.0664x over previous
#include <cuda_runtime.h>
#include <math.h>
#include <stdint.h>

#define BZ   128
#define T    32
#define D    768
#define DFF  3072
#define NE   8
#define NROWS 256
#define OUT_ELEMS (NROWS*T*D)
#define MAX_TILES 72

#define NT        256                 // CTA N tile
#define KC        32                  // K chunk
#define STAGES    3
#define AS_STRIDE 36                  // floats per A smem row
#define BS_STRIDE 264                 // floats per B smem k-row
#define A_STAGE   (128*AS_STRIDE)     // 4608 floats
#define B_STAGE   (KC*BS_STRIDE)      // 8448 floats
#define STAGE_FLOATS (A_STAGE + B_STAGE)       // 13056
#define SMEM_BYTES   (STAGES*STAGE_FLOATS*4)   // 156672

// ---------------- scratch ---------------------------------------------------
__device__ float g_xavg[BZ*D];
__device__ int   g_sel[NROWS];
__device__ int   g_perm[NROWS];
__device__ int   g_tile_e[MAX_TILES];
__device__ int   g_tile_p0[MAX_TILES];
__device__ int   g_tile_rows[MAX_TILES];
__device__ int   g_ntiles;
__device__ float g_xr[(size_t)BZ*T*D];       // tf32-rounded copy of x
__device__ float g_h[(size_t)NROWS*T*DFF];   // intermediate (tf32-rounded), grouped

__device__ __forceinline__ float gelu_exact(float v) {
    return 0.5f * v * (1.0f + erff(v * 0.70710678118654752f));
}
__device__ __forceinline__ uint32_t cvt_tf32(float f) {
    uint32_t u;
    asm("cvt.rna.tf32.f32 %0, %1;" : "=r"(u) : "f"(f));
    return u;
}
__device__ __forceinline__ void mma_tf32(float* c,
                                         uint32_t a0, uint32_t a1, uint32_t a2, uint32_t a3,
                                         uint32_t b0, uint32_t b1) {
    asm volatile(
        "mma.sync.aligned.m16n8k8.row.col.f32.tf32.tf32.f32 "
        "{%0,%1,%2,%3}, {%4,%5,%6,%7}, {%8,%9}, {%0,%1,%2,%3};"
        : "+f"(c[0]), "+f"(c[1]), "+f"(c[2]), "+f"(c[3])
        : "r"(a0), "r"(a1), "r"(a2), "r"(a3), "r"(b0), "r"(b1));
}
__device__ __forceinline__ void cp16(uint32_t saddr, const void* g) {
    asm volatile("cp.async.cg.shared.global [%0], [%1], 16;" :: "r"(saddr), "l"(g));
}

// ---------------- kernel 0: tf32-round x ------------------------------------
__global__ void round_x_kernel(const float* __restrict__ x) {
    int i = blockIdx.x * blockDim.x + threadIdx.x;
    const int n4 = BZ*T*D/4;
    if (i < n4) {
        float4 v = ((const float4*)x)[i];
        uint4 r = make_uint4(cvt_tf32(v.x), cvt_tf32(v.y), cvt_tf32(v.z), cvt_tf32(v.w));
        ((uint4*)g_xr)[i] = r;
    }
}

// ---------------- kernel 1: x_avg (raw x, full precision) -------------------
__global__ void avg_kernel(const float* __restrict__ x) {
    int b = blockIdx.x;
    for (int d = threadIdx.x; d < D; d += blockDim.x) {
        float s = 0.f;
        #pragma unroll
        for (int t = 0; t < T; t++) s += x[((size_t)b*T + t)*D + d];
        g_xavg[b*D + d] = s * (1.0f / T);
    }
}

// ---------------- kernel 2: router ------------------------------------------
__global__ void router_kernel(const float* __restrict__ Wg,
                              float* __restrict__ dout, int out_size) {
    int b = blockIdx.x;
    int lane = threadIdx.x;
    int e = lane & 7;
    int chunk = lane >> 3;
    float part = 0.f;
    const float* xa = g_xavg + b*D;
    for (int d = chunk*192; d < (chunk+1)*192; d++) part += xa[d] * Wg[d*NE + e];
    part += __shfl_down_sync(0xffffffffu, part, 16);
    part += __shfl_down_sync(0xffffffffu, part, 8);
    float lv[NE];
    #pragma unroll
    for (int i = 0; i < NE; i++) lv[i] = __shfl_sync(0xffffffffu, part, i);

    if (lane == 0) {
        float mx = lv[0];
        #pragma unroll
        for (int i = 1; i < NE; i++) mx = fmaxf(mx, lv[i]);
        float p[NE]; float sum = 0.f;
        #pragma unroll
        for (int i = 0; i < NE; i++) { p[i] = __expf(lv[i] - mx); sum += p[i]; }
        float inv = 1.0f / sum;
        #pragma unroll
        for (int i = 0; i < NE; i++) p[i] *= inv;
        int i0 = 0;
        #pragma unroll
        for (int i = 1; i < NE; i++) if (p[i] > p[i0]) i0 = i;
        int i1 = (i0 == 0) ? 1 : 0;
        #pragma unroll
        for (int i = 0; i < NE; i++) if (i != i0 && p[i] > p[i1]) i1 = i;
        g_sel[2*b] = i0; g_sel[2*b+1] = i1;
        if (out_size >= OUT_ELEMS + 2*NROWS) {
            dout[OUT_ELEMS + 2*b]             = p[i0];
            dout[OUT_ELEMS + 2*b + 1]         = p[i1];
            dout[OUT_ELEMS + NROWS + 2*b]     = (float)i0;
            dout[OUT_ELEMS + NROWS + 2*b + 1] = (float)i1;
        }
    }
}

// ---------------- kernel 3: group rows by expert (parallel, smem) -----------
__global__ void group_kernel() {
    __shared__ int ssel[NROWS];
    __shared__ int shist[NE];
    __shared__ int soff[NE];
    int t = threadIdx.x;
    if (t < NE) shist[t] = 0;
    __syncthreads();
    ssel[t] = g_sel[t];
    __syncthreads();
    atomicAdd(&shist[ssel[t]], 1);
    __syncthreads();
    if (t == 0) {
        int pos = 0, tiles = 0;
        for (int e = 0; e < NE; e++) {
            soff[e] = pos;
            int cnt = shist[e];
            for (int r = 0; r < cnt; r += 4) {
                g_tile_e[tiles] = e; g_tile_p0[tiles] = pos + r;
                g_tile_rows[tiles] = min(4, cnt - r); tiles++;
            }
            pos += cnt;
        }
        g_ntiles = tiles;
    }
    __syncthreads();
    // stable rank: #earlier rows with same expert
    int mysel = ssel[t], rank = 0;
    for (int m = 0; m < NROWS; m++)
        if (m < t && ssel[m] == mysel) rank++;
    g_perm[soff[mysel] + rank] = t;
}

// ---------------- tf32 mma.sync GEMM, cp.async 3-stage ----------------------
// PHASE 1: g_h = round(gelu(Xr_perm @ W1[e] + b1[e]));  K=768,  N=3072
// PHASE 2 (split-K=2): out[perm] += g_h @ W2[e](+b2 on kp0); K=1536/part
// CTA 128x256, 256 threads / 8 warps (2m x 4n), warp tile 64x64.
template<int PHASE>
__global__ __launch_bounds__(256, 1) void ffn_mma(
    const float* __restrict__ X,
    const float* __restrict__ W1, const float* __restrict__ b1,
    const float* __restrict__ W2, const float* __restrict__ b2,
    float* __restrict__ out)
{
    const int mt = blockIdx.x;
    if (mt >= g_ntiles) return;
    const int e     = g_tile_e[mt];
    const int p0    = g_tile_p0[mt];
    const int nrows = g_tile_rows[mt];
    const int kp    = (PHASE == 2) ? blockIdx.z : 0;
    const int NF    = (PHASE == 1) ? DFF : D;
    const int kbase = (PHASE == 2) ? kp * (DFF/2) : 0;
    const int NC    = ((PHASE == 1) ? D : DFF/2) / KC;
    const float* __restrict__ Bsrc = (PHASE == 1) ? (W1 + (size_t)e*D*DFF)
                                                  : (W2 + (size_t)e*DFF*D);
    const int n0 = blockIdx.y * NT;
    const int tid = threadIdx.x, wid = tid >> 5, lane = tid & 31;

    extern __shared__ float smf[];

    // ---- async loader assignment (256 threads) ----
    // A: 128 rows x 32 floats (8x16B); thread -> row tid>>1, 4 segs at (tid&1)*4+i
    // B: 32 k-rows x 256 floats (64x16B); thread -> row tid>>3, 8 segs at (tid&7)+8i
    const int arow = tid >> 1, aseg4 = (tid & 1) * 4;
    const int brow = tid >> 3, bseg = tid & 7;

    const float* aglob;
    {
        int r = ((arow >> 5) < nrows) ? arow : (arow & 31);  // clamp pad rows
        if (PHASE == 1) {
            int n = g_perm[p0 + (r >> 5)];
            aglob = g_xr + ((size_t)(n >> 1)*T + (r & 31)) * (size_t)D;
        } else {
            aglob = g_h + ((size_t)(p0*T + r)) * (size_t)DFF;
        }
    }
    const float* bglob = Bsrc + (size_t)brow*NF + n0;

    uint32_t sbase = (uint32_t)__cvta_generic_to_shared(smf);
    uint32_t aSts[STAGES], bSts[STAGES];
    #pragma unroll
    for (int s = 0; s < STAGES; s++) {
        aSts[s] = sbase + (s*STAGE_FLOATS + arow*AS_STRIDE)*4;
        bSts[s] = sbase + (s*STAGE_FLOATS + A_STAGE + brow*BS_STRIDE)*4;
    }

    #define ISSUE(k0, s) do {                                                 \
        _Pragma("unroll")                                                     \
        for (int i = 0; i < 4; i++)                                           \
            cp16(aSts[s] + (aseg4 + i)*16, aglob + (k0) + (aseg4 + i)*4);     \
        _Pragma("unroll")                                                     \
        for (int i = 0; i < 8; i++)                                           \
            cp16(bSts[s] + (bseg + 8*i)*16,                                   \
                 bglob + (size_t)(k0)*NF + (bseg + 8*i)*4);                   \
    } while (0)

    // ---- mma fragment bases (per stage); warp tile 64x64 ----
    const int wm = (wid & 1) * 64;
    const int wn = (wid >> 1) * 64;
    const int g  = lane >> 2;
    const int t  = lane & 3;
    const float* Abf[STAGES];
    const float* Bbf[STAGES];
    #pragma unroll
    for (int s = 0; s < STAGES; s++) {
        Abf[s] = smf + s*STAGE_FLOATS + (wm + g)*AS_STRIDE + t;
        Bbf[s] = smf + s*STAGE_FLOATS + A_STAGE + t*BS_STRIDE + wn + g;
    }

    float acc[4][8][4];
    #pragma unroll
    for (int i = 0; i < 4; i++)
        #pragma unroll
        for (int j = 0; j < 8; j++)
            #pragma unroll
            for (int q = 0; q < 4; q++) acc[i][j][q] = 0.f;

    // A data pre-rounded (g_xr / g_h stored rounded): raw bit reuse.
    #define CONSUME(Ab, Bb) do {                                              \
        _Pragma("unroll")                                                     \
        for (int ks = 0; ks < 4; ks++) {                                      \
            uint32_t af[4][4], bf[8][2];                                      \
            _Pragma("unroll")                                                 \
            for (int mi = 0; mi < 4; mi++) {                                  \
                af[mi][0] = __float_as_uint((Ab)[mi*16*AS_STRIDE + ks*8]);    \
                af[mi][1] = __float_as_uint((Ab)[mi*16*AS_STRIDE + ks*8 + 8*AS_STRIDE]); \
                af[mi][2] = __float_as_uint((Ab)[mi*16*AS_STRIDE + ks*8 + 4]);\
                af[mi][3] = __float_as_uint((Ab)[mi*16*AS_STRIDE + ks*8 + 8*AS_STRIDE + 4]); \
            }                                                                 \
            _Pragma("unroll")                                                 \
            for (int ni = 0; ni < 8; ni++) {                                  \
                bf[ni][0] = cvt_tf32((Bb)[ks*8*BS_STRIDE + ni*8]);            \
                bf[ni][1] = cvt_tf32((Bb)[ks*8*BS_STRIDE + ni*8 + 4*BS_STRIDE]); \
            }                                                                 \
            _Pragma("unroll")                                                 \
            for (int mi = 0; mi < 4; mi++)                                    \
                _Pragma("unroll")                                             \
                for (int ni = 0; ni < 8; ni++)                                \
                    mma_tf32(acc[mi][ni], af[mi][0], af[mi][1], af[mi][2],    \
                             af[mi][3], bf[ni][0], bf[ni][1]);                \
        }                                                                     \
    } while (0)

    // ---- prologue: chunks 0,1 in flight ----
    ISSUE(kbase, 0);
    asm volatile("cp.async.commit_group;" ::: "memory");
    ISSUE(kbase + KC, 1);
    asm volatile("cp.async.commit_group;" ::: "memory");

    // ---- main loop: single barrier per chunk ----
    for (int c = 0; c < NC; c++) {
        asm volatile("cp.async.wait_group 1;" ::: "memory");
        __syncthreads();                 // chunk c visible; consume(c-1) done
        if (c + 2 < NC) ISSUE(kbase + (c + 2)*KC, (c + 2) % STAGES);
        asm volatile("cp.async.commit_group;" ::: "memory");
        switch (c % STAGES) {
            case 0: CONSUME(Abf[0], Bbf[0]); break;
            case 1: CONSUME(Abf[1], Bbf[1]); break;
            default: CONSUME(Abf[2], Bbf[2]); break;
        }
    }

    // ---- epilogue ----
    const float* bias = (PHASE == 1) ? (b1 + e*DFF + n0) : (b2 + e*D + n0);
    #pragma unroll
    for (int mi = 0; mi < 4; mi++) {
        #pragma unroll
        for (int h = 0; h < 2; h++) {
            int r = wm + 16*mi + g + 8*h;
            int br = r >> 5;
            if (br >= nrows) continue;
            if (PHASE == 1) {
                float* dst = g_h + ((size_t)(p0*T + r)) * (size_t)DFF + n0;
                #pragma unroll
                for (int ni = 0; ni < 8; ni++) {
                    int col = wn + 8*ni + 2*t;
                    float v0 = gelu_exact(acc[mi][ni][2*h + 0] + bias[col]);
                    float v1 = gelu_exact(acc[mi][ni][2*h + 1] + bias[col + 1]);
                    uint2 w = make_uint2(cvt_tf32(v0), cvt_tf32(v1));
                    *(uint2*)(dst + col) = w;
                }
            } else {
                int n = g_perm[p0 + br];
                float* dst = out + ((size_t)n*T + (r & 31)) * (size_t)D + n0;
                #pragma unroll
                for (int ni = 0; ni < 8; ni++) {
                    int col = wn + 8*ni + 2*t;
                    float v0 = acc[mi][ni][2*h + 0];
                    float v1 = acc[mi][ni][2*h + 1];
                    if (kp == 0) { v0 += bias[col]; v1 += bias[col + 1]; }
                    // exactly 2 atomic contributions per element onto 0-init:
                    // order-invariant -> deterministic
                    atomicAdd(dst + col,     v0);
                    atomicAdd(dst + col + 1, v1);
                }
            }
        }
    }
    #undef ISSUE
    #undef CONSUME
}

// ---------------- launch ----------------------------------------------------
extern "C" void kernel_launch(void* const* d_in, const int* in_sizes, int n_in,
                              void* d_out, int out_size) {
    const float* x  = (const float*)d_in[0];
    const float* Wg = (const float*)d_in[2];
    const float* W1 = (const float*)d_in[3];
    const float* b1 = (const float*)d_in[4];
    const float* W2 = (const float*)d_in[5];
    const float* b2 = (const float*)d_in[6];
    float* out = (float*)d_out;

    cudaFuncSetAttribute(ffn_mma<1>, cudaFuncAttributeMaxDynamicSharedMemorySize, SMEM_BYTES);
    cudaFuncSetAttribute(ffn_mma<2>, cudaFuncAttributeMaxDynamicSharedMemorySize, SMEM_BYTES);

    cudaMemsetAsync(out, 0, (size_t)out_size * sizeof(float));
    round_x_kernel<<<(BZ*T*D/4 + 255)/256, 256>>>(x);
    avg_kernel<<<BZ, 256>>>(x);
    router_kernel<<<BZ, 32>>>(Wg, out, out_size);
    group_kernel<<<1, NROWS>>>();
    ffn_mma<1><<<dim3(MAX_TILES, DFF/NT),  256, SMEM_BYTES>>>(x, W1, b1, W2, b2, out);
    ffn_mma<2><<<dim3(MAX_TILES, D/NT, 2), 256, SMEM_BYTES>>>(x, W1, b1, W2, b2, out);
}